// round 1
// baseline (speedup 1.0000x reference)
#include <cuda_runtime.h>

#define NN      100000
#define INC     512
#define HID     256
#define OUTC    128
#define EMAX    1600000
#define KSTEPS  10
#define ALPHA_F 0.1f
#define ONEMA_F 0.9f
#define LNEPS   1e-5f

// ---------------- static device scratch (no allocation allowed) ----------------
__device__ float g_h1[(size_t)NN * HID];
__device__ float g_h2[(size_t)NN * HID];
__device__ float g_h0[(size_t)NN * OUTC];
__device__ float g_bufA[(size_t)NN * OUTC];
__device__ float g_bufB[(size_t)NN * OUTC];
__device__ float g_deg[NN];
__device__ float g_norm[EMAX];

// ---------------- fp32 SGEMM: C[M,N] = A[M,K] @ B[K,N] + bias[N] ----------------
// 64x64 tile, 256 threads, 4x4 per thread, K-tile 16, float4 vectorized.
__global__ void sgemm_bias(const float* __restrict__ A, const float* __restrict__ B,
                           const float* __restrict__ bias, float* __restrict__ C,
                           int M, int K, int N)
{
    __shared__ float sA[16][64];   // [k][m]
    __shared__ float sB[16][64];   // [k][n]

    const int tid = threadIdx.x;            // 0..255
    const int bm  = blockIdx.y * 64;
    const int bn  = blockIdx.x * 64;
    const int tx  = tid & 15;               // n-group
    const int ty  = tid >> 4;               // m-group

    // A-load mapping: row = tid>>2 (0..63), k-quad = (tid&3)*4
    const int a_row = tid >> 2;
    const int a_kq  = (tid & 3) * 4;
    const bool m_ok = (bm + a_row) < M;
    // B-load mapping: k = tid>>4 (0..15), n-quad = (tid&15)*4
    const int b_k = tid >> 4;
    const int b_n = (tid & 15) * 4;

    float acc[4][4] = {};

    for (int k0 = 0; k0 < K; k0 += 16) {
        float4 av = m_ok ? *(const float4*)(A + (size_t)(bm + a_row) * K + (k0 + a_kq))
                         : make_float4(0.f, 0.f, 0.f, 0.f);
        sA[a_kq + 0][a_row] = av.x;
        sA[a_kq + 1][a_row] = av.y;
        sA[a_kq + 2][a_row] = av.z;
        sA[a_kq + 3][a_row] = av.w;
        *(float4*)&sB[b_k][b_n] =
            *(const float4*)(B + (size_t)(k0 + b_k) * N + (bn + b_n));
        __syncthreads();

        #pragma unroll
        for (int kk = 0; kk < 16; kk++) {
            float4 a4 = *(const float4*)&sA[kk][ty * 4];
            float4 b4 = *(const float4*)&sB[kk][tx * 4];
            float a[4] = {a4.x, a4.y, a4.z, a4.w};
            float b[4] = {b4.x, b4.y, b4.z, b4.w};
            #pragma unroll
            for (int i = 0; i < 4; i++)
                #pragma unroll
                for (int j = 0; j < 4; j++)
                    acc[i][j] = fmaf(a[i], b[j], acc[i][j]);
        }
        __syncthreads();
    }

    #pragma unroll
    for (int i = 0; i < 4; i++) {
        int m = bm + ty * 4 + i;
        if (m < M) {
            #pragma unroll
            for (int j = 0; j < 4; j++) {
                int n = bn + tx * 4 + j;
                C[(size_t)m * N + n] = acc[i][j] + bias[n];
            }
        }
    }
}

// ---------------- fused LayerNorm + ReLU over rows of HID=256 (warp per row) ----
__global__ void ln_relu_kernel(float* __restrict__ h, const float* __restrict__ g,
                               const float* __restrict__ be, int M)
{
    int warp = (blockIdx.x * blockDim.x + threadIdx.x) >> 5;
    if (warp >= M) return;
    int lane = threadIdx.x & 31;

    float4* row = (float4*)(h + (size_t)warp * HID);
    float4 v0 = row[lane];
    float4 v1 = row[lane + 32];

    float s  = v0.x + v0.y + v0.z + v0.w + v1.x + v1.y + v1.z + v1.w;
    float sq = v0.x * v0.x + v0.y * v0.y + v0.z * v0.z + v0.w * v0.w
             + v1.x * v1.x + v1.y * v1.y + v1.z * v1.z + v1.w * v1.w;
    #pragma unroll
    for (int o = 16; o > 0; o >>= 1) {
        s  += __shfl_xor_sync(0xffffffffu, s, o);
        sq += __shfl_xor_sync(0xffffffffu, sq, o);
    }
    float mu   = s * (1.0f / 256.0f);
    float var  = sq * (1.0f / 256.0f) - mu * mu;
    float rstd = rsqrtf(var + LNEPS);

    const float4* g4 = (const float4*)g;
    const float4* b4 = (const float4*)be;
    float4 G0 = g4[lane], G1 = g4[lane + 32];
    float4 B0 = b4[lane], B1 = b4[lane + 32];

    v0.x = fmaxf((v0.x - mu) * rstd * G0.x + B0.x, 0.f);
    v0.y = fmaxf((v0.y - mu) * rstd * G0.y + B0.y, 0.f);
    v0.z = fmaxf((v0.z - mu) * rstd * G0.z + B0.z, 0.f);
    v0.w = fmaxf((v0.w - mu) * rstd * G0.w + B0.w, 0.f);
    v1.x = fmaxf((v1.x - mu) * rstd * G1.x + B1.x, 0.f);
    v1.y = fmaxf((v1.y - mu) * rstd * G1.y + B1.y, 0.f);
    v1.z = fmaxf((v1.z - mu) * rstd * G1.z + B1.z, 0.f);
    v1.w = fmaxf((v1.w - mu) * rstd * G1.w + B1.w, 0.f);

    row[lane]      = v0;
    row[lane + 32] = v1;
}

// ---------------- graph prep ---------------------------------------------------
__global__ void deg_init_kernel(float* __restrict__ deg)
{
    int i = blockIdx.x * blockDim.x + threadIdx.x;
    if (i < NN) deg[i] = 1.0f;   // self loop
}

__global__ void deg_count_kernel(const int* __restrict__ dst, float* __restrict__ deg, int E)
{
    int e = blockIdx.x * blockDim.x + threadIdx.x;
    if (e < E) atomicAdd(&deg[dst[e]], 1.0f);
}

__global__ void norm_kernel(const int* __restrict__ src, const int* __restrict__ dst,
                            const float* __restrict__ deg, float* __restrict__ nrm, int E)
{
    int e = blockIdx.x * blockDim.x + threadIdx.x;
    if (e < E) nrm[e] = rsqrtf(deg[src[e]]) * rsqrtf(deg[dst[e]]);
}

// ---------------- APPNP step: init with teleport + self loop --------------------
// out[i][:] = alpha*h0[i][:] + (1-alpha)*(1/deg[i])*carry[i][:]
__global__ void appnp_init_kernel(const float* __restrict__ h0,
                                  const float* __restrict__ carry,
                                  const float* __restrict__ deg,
                                  float* __restrict__ out)
{
    int idx = blockIdx.x * blockDim.x + threadIdx.x;  // over NN*32 float4s
    if (idx >= NN * (OUTC / 4)) return;
    int node = idx >> 5;
    float sw = ONEMA_F / deg[node];
    float4 c = ((const float4*)carry)[idx];
    float4 h = ((const float4*)h0)[idx];
    float4 o;
    o.x = fmaf(ALPHA_F, h.x, sw * c.x);
    o.y = fmaf(ALPHA_F, h.y, sw * c.y);
    o.z = fmaf(ALPHA_F, h.z, sw * c.z);
    o.w = fmaf(ALPHA_F, h.w, sw * c.w);
    ((float4*)out)[idx] = o;
}

// ---------------- APPNP edge scatter: warp per edge, vector reds ----------------
__global__ void appnp_edge_kernel(const int* __restrict__ src, const int* __restrict__ dst,
                                  const float* __restrict__ nrm,
                                  const float* __restrict__ carry,
                                  float* __restrict__ out, int E)
{
    int e = (blockIdx.x * blockDim.x + threadIdx.x) >> 5;
    if (e >= E) return;
    int lane = threadIdx.x & 31;

    int si = src[e];
    int di = dst[e];
    float w = nrm[e] * ONEMA_F;

    float4 v = ((const float4*)(carry + (size_t)si * OUTC))[lane];
    float4 r;
    r.x = w * v.x; r.y = w * v.y; r.z = w * v.z; r.w = w * v.w;

    float* p = out + (size_t)di * OUTC + lane * 4;
    asm volatile("red.global.add.v4.f32 [%0], {%1, %2, %3, %4};"
                 :: "l"(p), "f"(r.x), "f"(r.y), "f"(r.z), "f"(r.w)
                 : "memory");
}

// ---------------- launch --------------------------------------------------------
extern "C" void kernel_launch(void* const* d_in, const int* in_sizes, int n_in,
                              void* d_out, int out_size)
{
    const float* x     = (const float*)d_in[0];
    const int*   ei    = (const int*)  d_in[1];
    const float* W_in  = (const float*)d_in[2];
    const float* b_in  = (const float*)d_in[3];
    const float* W1    = (const float*)d_in[4];
    const float* b1    = (const float*)d_in[5];
    const float* g1    = (const float*)d_in[6];
    const float* be1   = (const float*)d_in[7];
    const float* W2    = (const float*)d_in[8];
    const float* b2    = (const float*)d_in[9];
    const float* g2    = (const float*)d_in[10];
    const float* be2   = (const float*)d_in[11];
    const float* W_out = (const float*)d_in[12];
    const float* b_out = (const float*)d_in[13];
    float* out = (float*)d_out;

    int E = in_sizes[1] / 2;
    if (E > EMAX) E = EMAX;
    const int* src = ei;
    const int* dst = ei + E;

    float *h1, *h2, *h0, *bA, *bB, *deg, *nrm;
    cudaGetSymbolAddress((void**)&h1,  g_h1);
    cudaGetSymbolAddress((void**)&h2,  g_h2);
    cudaGetSymbolAddress((void**)&h0,  g_h0);
    cudaGetSymbolAddress((void**)&bA,  g_bufA);
    cudaGetSymbolAddress((void**)&bB,  g_bufB);
    cudaGetSymbolAddress((void**)&deg, g_deg);
    cudaGetSymbolAddress((void**)&nrm, g_norm);

    const int mt = (NN + 63) / 64;   // 1563 row-tiles

    // ---- MLP ----
    sgemm_bias<<<dim3(HID / 64, mt), 256>>>(x,  W_in,  b_in,  h1, NN, INC, HID);
    sgemm_bias<<<dim3(HID / 64, mt), 256>>>(h1, W1,    b1,    h2, NN, HID, HID);
    ln_relu_kernel<<<(NN * 32 + 255) / 256, 256>>>(h2, g1, be1, NN);
    sgemm_bias<<<dim3(HID / 64, mt), 256>>>(h2, W2,    b2,    h1, NN, HID, HID);
    ln_relu_kernel<<<(NN * 32 + 255) / 256, 256>>>(h1, g2, be2, NN);
    sgemm_bias<<<dim3(OUTC / 64, mt), 256>>>(h1, W_out, b_out, h0, NN, HID, OUTC);

    // ---- graph prep (recomputed every call; no caching allowed) ----
    deg_init_kernel<<<(NN + 255) / 256, 256>>>(deg);
    deg_count_kernel<<<(E + 255) / 256, 256>>>(dst, deg, E);
    norm_kernel<<<(E + 255) / 256, 256>>>(src, dst, deg, nrm, E);

    // ---- APPNP: 10 propagation steps, ping-pong buffers, last writes d_out ----
    const float* carry = h0;
    const int init_blocks = (NN * (OUTC / 4) + 255) / 256;
    const int edge_blocks = ((E * 32) + 255) / 256;
    for (int t = 0; t < KSTEPS; t++) {
        float* o = (t == KSTEPS - 1) ? out : ((t & 1) ? bB : bA);
        appnp_init_kernel<<<init_blocks, 256>>>(h0, carry, deg, o);
        appnp_edge_kernel<<<edge_blocks, 256>>>(src, dst, nrm, carry, o, E);
        carry = o;
    }
}

// round 2
// speedup vs baseline: 1.6715x; 1.6715x over previous
#include <cuda_runtime.h>

#define NN      100000
#define INC     512
#define HID     256
#define OUTC    128
#define EMAX    1600000
#define KSTEPS  10
#define ALPHA_F 0.1f
#define ONEMA_F 0.9f
#define LNEPS   1e-5f

// ---------------- static device scratch (no allocation allowed) ----------------
__device__ float g_h1[(size_t)NN * HID];
__device__ float g_h2[(size_t)NN * HID];
__device__ float g_h0[(size_t)NN * OUTC];
__device__ float g_bufA[(size_t)NN * OUTC];
__device__ float g_bufB[(size_t)NN * OUTC];
__device__ float g_dis[NN];            // rsqrt(deg)
__device__ int   g_cnt[NN];            // in-degree (no self loop)
__device__ int   g_fill[NN];           // fill cursors
__device__ int   g_rowptr[NN + 1];
__device__ int   g_csr_src[EMAX];
__device__ float g_csr_w[EMAX];
__device__ int   g_bsum[512];          // block sums for scan (391 used)

// ---------------- fp32 SGEMM: C[M,N] = A[M,K]@B[K,N] + bias[N] ------------------
// 128x128 tile, 256 threads, 8x8 micro-tile, K-tile 8. LDS:FFMA = 1:16.
__global__ void __launch_bounds__(256, 2)
sgemm_bias(const float* __restrict__ A, const float* __restrict__ B,
           const float* __restrict__ bias, float* __restrict__ C,
           int M, int K, int N)
{
    __shared__ float sA[8][128];   // [k][m]
    __shared__ float sB[8][128];   // [k][n]

    const int tid = threadIdx.x;
    const int bm  = blockIdx.y * 128;
    const int bn  = blockIdx.x * 128;
    const int tx  = tid & 15;          // n-group (0..15)
    const int ty  = tid >> 4;          // m-group (0..15)

    // A-load: row = tid>>1 (0..127), k-quad = (tid&1)*4
    const int a_row = tid >> 1;
    const int a_k4  = (tid & 1) * 4;
    const bool m_ok = (bm + a_row) < M;
    // B-load: k = tid>>5 (0..7), n-quad = (tid&31)*4
    const int b_k = tid >> 5;
    const int b_n = (tid & 31) * 4;

    float acc[8][8] = {};

    for (int k0 = 0; k0 < K; k0 += 8) {
        float4 av = m_ok ? *(const float4*)(A + (size_t)(bm + a_row) * K + (k0 + a_k4))
                         : make_float4(0.f, 0.f, 0.f, 0.f);
        sA[a_k4 + 0][a_row] = av.x;
        sA[a_k4 + 1][a_row] = av.y;
        sA[a_k4 + 2][a_row] = av.z;
        sA[a_k4 + 3][a_row] = av.w;
        *(float4*)&sB[b_k][b_n] =
            *(const float4*)(B + (size_t)(k0 + b_k) * N + (bn + b_n));
        __syncthreads();

        #pragma unroll
        for (int kk = 0; kk < 8; kk++) {
            float4 a0 = *(const float4*)&sA[kk][ty * 8];
            float4 a1 = *(const float4*)&sA[kk][ty * 8 + 4];
            float4 b0 = *(const float4*)&sB[kk][tx * 8];
            float4 b1 = *(const float4*)&sB[kk][tx * 8 + 4];
            float a[8] = {a0.x, a0.y, a0.z, a0.w, a1.x, a1.y, a1.z, a1.w};
            float b[8] = {b0.x, b0.y, b0.z, b0.w, b1.x, b1.y, b1.z, b1.w};
            #pragma unroll
            for (int i = 0; i < 8; i++)
                #pragma unroll
                for (int j = 0; j < 8; j++)
                    acc[i][j] = fmaf(a[i], b[j], acc[i][j]);
        }
        __syncthreads();
    }

    #pragma unroll
    for (int i = 0; i < 8; i++) {
        int m = bm + ty * 8 + i;
        if (m < M) {
            #pragma unroll
            for (int j = 0; j < 8; j++) {
                int n = bn + tx * 8 + j;
                C[(size_t)m * N + n] = acc[i][j] + bias[n];
            }
        }
    }
}

// ---------------- fused LayerNorm + ReLU over rows of HID=256 (warp per row) ----
__global__ void ln_relu_kernel(float* __restrict__ h, const float* __restrict__ g,
                               const float* __restrict__ be, int M)
{
    int warp = (blockIdx.x * blockDim.x + threadIdx.x) >> 5;
    if (warp >= M) return;
    int lane = threadIdx.x & 31;

    float4* row = (float4*)(h + (size_t)warp * HID);
    float4 v0 = row[lane];
    float4 v1 = row[lane + 32];

    float s  = v0.x + v0.y + v0.z + v0.w + v1.x + v1.y + v1.z + v1.w;
    float sq = v0.x * v0.x + v0.y * v0.y + v0.z * v0.z + v0.w * v0.w
             + v1.x * v1.x + v1.y * v1.y + v1.z * v1.z + v1.w * v1.w;
    #pragma unroll
    for (int o = 16; o > 0; o >>= 1) {
        s  += __shfl_xor_sync(0xffffffffu, s, o);
        sq += __shfl_xor_sync(0xffffffffu, sq, o);
    }
    float mu   = s * (1.0f / 256.0f);
    float var  = sq * (1.0f / 256.0f) - mu * mu;
    float rstd = rsqrtf(var + LNEPS);

    const float4* g4 = (const float4*)g;
    const float4* b4 = (const float4*)be;
    float4 G0 = g4[lane], G1 = g4[lane + 32];
    float4 B0 = b4[lane], B1 = b4[lane + 32];

    v0.x = fmaxf((v0.x - mu) * rstd * G0.x + B0.x, 0.f);
    v0.y = fmaxf((v0.y - mu) * rstd * G0.y + B0.y, 0.f);
    v0.z = fmaxf((v0.z - mu) * rstd * G0.z + B0.z, 0.f);
    v0.w = fmaxf((v0.w - mu) * rstd * G0.w + B0.w, 0.f);
    v1.x = fmaxf((v1.x - mu) * rstd * G1.x + B1.x, 0.f);
    v1.y = fmaxf((v1.y - mu) * rstd * G1.y + B1.y, 0.f);
    v1.z = fmaxf((v1.z - mu) * rstd * G1.z + B1.z, 0.f);
    v1.w = fmaxf((v1.w - mu) * rstd * G1.w + B1.w, 0.f);

    row[lane]      = v0;
    row[lane + 32] = v1;
}

// ---------------- graph prep: CSR by dst ---------------------------------------
__global__ void zero_kernel(int* __restrict__ cnt, int* __restrict__ fill)
{
    int i = blockIdx.x * blockDim.x + threadIdx.x;
    if (i < NN) { cnt[i] = 0; fill[i] = 0; }
}

__global__ void deg_count_kernel(const int* __restrict__ dst, int* __restrict__ cnt, int E)
{
    int e = blockIdx.x * blockDim.x + threadIdx.x;
    if (e < E) atomicAdd(&cnt[dst[e]], 1);
}

__global__ void dis_kernel(const int* __restrict__ cnt, float* __restrict__ dis)
{
    int i = blockIdx.x * blockDim.x + threadIdx.x;
    if (i < NN) dis[i] = rsqrtf((float)(cnt[i] + 1));   // +1 self loop
}

// block-local exclusive scan of cnt into rowptr; block totals to bsum
__global__ void scan_partial(const int* __restrict__ cnt, int* __restrict__ rowptr,
                             int* __restrict__ bsum)
{
    __shared__ int s[256];
    int tid = threadIdx.x;
    int i = blockIdx.x * 256 + tid;
    int v = (i < NN) ? cnt[i] : 0;
    s[tid] = v;
    __syncthreads();
    #pragma unroll
    for (int o = 1; o < 256; o <<= 1) {
        int t = 0;
        if (tid >= o) t = s[tid - o];
        __syncthreads();
        if (tid >= o) s[tid] += t;
        __syncthreads();
    }
    if (i < NN) rowptr[i] = s[tid] - v;      // block-local exclusive
    if (tid == 255) bsum[blockIdx.x] = s[255];
}

// single-block exclusive scan of the 391 block sums (in-place)
__global__ void scan_bsums(int* __restrict__ bsum, int nb)
{
    __shared__ int s[512];
    int tid = threadIdx.x;
    int v = (tid < nb) ? bsum[tid] : 0;
    s[tid] = v;
    __syncthreads();
    #pragma unroll
    for (int o = 1; o < 512; o <<= 1) {
        int t = 0;
        if (tid >= o) t = s[tid - o];
        __syncthreads();
        if (tid >= o) s[tid] += t;
        __syncthreads();
    }
    if (tid < nb) bsum[tid] = s[tid] - v;    // exclusive
}

__global__ void add_offsets(int* __restrict__ rowptr, const int* __restrict__ bsum, int E)
{
    int i = blockIdx.x * blockDim.x + threadIdx.x;
    if (i < NN) rowptr[i] += bsum[i >> 8];
    if (i == 0) rowptr[NN] = E;
}

__global__ void fill_kernel(const int* __restrict__ src, const int* __restrict__ dst,
                            const float* __restrict__ dis,
                            const int* __restrict__ rowptr, int* __restrict__ fill,
                            int* __restrict__ csr_src, float* __restrict__ csr_w, int E)
{
    int e = blockIdx.x * blockDim.x + threadIdx.x;
    if (e >= E) return;
    int si = src[e];
    int di = dst[e];
    int p = rowptr[di] + atomicAdd(&fill[di], 1);
    csr_src[p] = si;
    csr_w[p]   = ONEMA_F * dis[si] * dis[di];
}

// ---------------- APPNP fused step: warp per node, pull aggregation ------------
// out[i] = alpha*h0[i] + (1-alpha)/deg[i]*carry[i] + sum_e w_e * carry[src_e]
__global__ void appnp_step_kernel(const int* __restrict__ rowptr,
                                  const int* __restrict__ csr_src,
                                  const float* __restrict__ csr_w,
                                  const float* __restrict__ dis,
                                  const float* __restrict__ h0,
                                  const float* __restrict__ carry,
                                  float* __restrict__ out)
{
    int node = (blockIdx.x * blockDim.x + threadIdx.x) >> 5;
    if (node >= NN) return;
    int lane = threadIdx.x & 31;

    const float4* c4 = (const float4*)carry;
    int beg = rowptr[node];
    int end = rowptr[node + 1];
    float ds = dis[node];
    float wself = ONEMA_F * ds * ds;

    float4 cv = c4[node * 32 + lane];
    float4 acc;
    acc.x = wself * cv.x; acc.y = wself * cv.y;
    acc.z = wself * cv.z; acc.w = wself * cv.w;

    int e = beg;
    // 2-way software pipeline over in-edges
    for (; e + 1 < end; e += 2) {
        int   s0 = __ldg(&csr_src[e]);
        int   s1 = __ldg(&csr_src[e + 1]);
        float w0 = __ldg(&csr_w[e]);
        float w1 = __ldg(&csr_w[e + 1]);
        float4 v0 = c4[s0 * 32 + lane];
        float4 v1 = c4[s1 * 32 + lane];
        acc.x = fmaf(w0, v0.x, acc.x); acc.y = fmaf(w0, v0.y, acc.y);
        acc.z = fmaf(w0, v0.z, acc.z); acc.w = fmaf(w0, v0.w, acc.w);
        acc.x = fmaf(w1, v1.x, acc.x); acc.y = fmaf(w1, v1.y, acc.y);
        acc.z = fmaf(w1, v1.z, acc.z); acc.w = fmaf(w1, v1.w, acc.w);
    }
    if (e < end) {
        int   s0 = __ldg(&csr_src[e]);
        float w0 = __ldg(&csr_w[e]);
        float4 v0 = c4[s0 * 32 + lane];
        acc.x = fmaf(w0, v0.x, acc.x); acc.y = fmaf(w0, v0.y, acc.y);
        acc.z = fmaf(w0, v0.z, acc.z); acc.w = fmaf(w0, v0.w, acc.w);
    }

    float4 h = ((const float4*)h0)[node * 32 + lane];
    float4 o;
    o.x = fmaf(ALPHA_F, h.x, acc.x);
    o.y = fmaf(ALPHA_F, h.y, acc.y);
    o.z = fmaf(ALPHA_F, h.z, acc.z);
    o.w = fmaf(ALPHA_F, h.w, acc.w);
    ((float4*)out)[node * 32 + lane] = o;
}

// ---------------- launch --------------------------------------------------------
extern "C" void kernel_launch(void* const* d_in, const int* in_sizes, int n_in,
                              void* d_out, int out_size)
{
    const float* x     = (const float*)d_in[0];
    const int*   ei    = (const int*)  d_in[1];
    const float* W_in  = (const float*)d_in[2];
    const float* b_in  = (const float*)d_in[3];
    const float* W1    = (const float*)d_in[4];
    const float* b1    = (const float*)d_in[5];
    const float* g1    = (const float*)d_in[6];
    const float* be1   = (const float*)d_in[7];
    const float* W2    = (const float*)d_in[8];
    const float* b2    = (const float*)d_in[9];
    const float* g2    = (const float*)d_in[10];
    const float* be2   = (const float*)d_in[11];
    const float* W_out = (const float*)d_in[12];
    const float* b_out = (const float*)d_in[13];
    float* out = (float*)d_out;

    int E = in_sizes[1] / 2;
    if (E > EMAX) E = EMAX;
    const int* src = ei;
    const int* dst = ei + E;

    float *h1, *h2, *h0, *bA, *bB, *dis, *csr_w;
    int *cnt, *fill, *rowptr, *csr_src, *bsum;
    cudaGetSymbolAddress((void**)&h1,      g_h1);
    cudaGetSymbolAddress((void**)&h2,      g_h2);
    cudaGetSymbolAddress((void**)&h0,      g_h0);
    cudaGetSymbolAddress((void**)&bA,      g_bufA);
    cudaGetSymbolAddress((void**)&bB,      g_bufB);
    cudaGetSymbolAddress((void**)&dis,     g_dis);
    cudaGetSymbolAddress((void**)&cnt,     g_cnt);
    cudaGetSymbolAddress((void**)&fill,    g_fill);
    cudaGetSymbolAddress((void**)&rowptr,  g_rowptr);
    cudaGetSymbolAddress((void**)&csr_src, g_csr_src);
    cudaGetSymbolAddress((void**)&csr_w,   g_csr_w);
    cudaGetSymbolAddress((void**)&bsum,    g_bsum);

    const int mt  = (NN + 127) / 128;          // 782 row-tiles
    const int nb  = (NN + 255) / 256;          // 391 scan blocks
    const int ne  = (E + 255) / 256;

    // ---- graph prep (recomputed every call; no caching allowed) ----
    zero_kernel<<<nb, 256>>>(cnt, fill);
    deg_count_kernel<<<ne, 256>>>(dst, cnt, E);
    dis_kernel<<<nb, 256>>>(cnt, dis);
    scan_partial<<<nb, 256>>>(cnt, rowptr, bsum);
    scan_bsums<<<1, 512>>>(bsum, nb);
    add_offsets<<<nb, 256>>>(rowptr, bsum, E);
    fill_kernel<<<ne, 256>>>(src, dst, dis, rowptr, fill, csr_src, csr_w, E);

    // ---- MLP ----
    sgemm_bias<<<dim3(HID / 128, mt), 256>>>(x,  W_in,  b_in,  h1, NN, INC, HID);
    sgemm_bias<<<dim3(HID / 128, mt), 256>>>(h1, W1,    b1,    h2, NN, HID, HID);
    ln_relu_kernel<<<(NN * 32 + 255) / 256, 256>>>(h2, g1, be1, NN);
    sgemm_bias<<<dim3(HID / 128, mt), 256>>>(h2, W2,    b2,    h1, NN, HID, HID);
    ln_relu_kernel<<<(NN * 32 + 255) / 256, 256>>>(h1, g2, be2, NN);
    sgemm_bias<<<dim3(OUTC / 128, mt), 256>>>(h1, W_out, b_out, h0, NN, HID, OUTC);

    // ---- APPNP: 10 fused pull steps, ping-pong, last writes d_out ----
    const float* carry = h0;
    const int step_blocks = (NN * 32 + 255) / 256;
    for (int t = 0; t < KSTEPS; t++) {
        float* o = (t == KSTEPS - 1) ? out : ((t & 1) ? bB : bA);
        appnp_step_kernel<<<step_blocks, 256>>>(rowptr, csr_src, csr_w, dis, h0, carry, o);
        carry = o;
    }
}